// round 2
// baseline (speedup 1.0000x reference)
#include <cuda_runtime.h>
#include <math.h>

// ---------------- problem constants ----------------
#define BATCH   4
#define CDIM    512
#define HH      64
#define WW2     64
#define HWTOK   4096          // 64*64
#define GWIN    1024          // 32*32 windows per batch
#define NHEADS_H 4
#define NHEADS_L 4
#define HEADD   64
#define HDIM    256
#define LDIM    256
#define ATT_SCALE 0.125f      // 64^-0.5

// ---------------- scratch (device globals; no allocation allowed) ----------------
__device__ float g_pooledT[CDIM * (BATCH * GWIN)];            // [c][b*G+g]      8 MB
__device__ float g_qkvq[(size_t)BATCH * HWTOK * 1024];        // [b*4096+tok][1024] (qkv_hi 768 | q_lo 256)  67 MB
__device__ float g_lkv[BATCH * GWIN * 512];                   // [b*1024+g][512] (k 256 | v 256)  8 MB
__device__ float g_hiat[(size_t)BATCH * HWTOK * HDIM];        // hi attention out, row-major  16.8 MB
__device__ float g_loat[(size_t)BATCH * HWTOK * LDIM];        // lo attention out, row-major  16.8 MB

// ---------------- kernel 1: window pooling (mean of 2x2), stored transposed ----------------
__global__ void pool_kernel(const float* __restrict__ x)
{
    int idx = blockIdx.x * blockDim.x + threadIdx.x;
    if (idx >= CDIM * BATCH * GWIN) return;
    int bg = idx & 4095;          // b*1024+g
    int c  = idx >> 12;
    int b  = bg >> 10;
    int g  = bg & 1023;
    int gh = g >> 5, gw = g & 31;
    const float* p = x + (size_t)b * CDIM * HWTOK + (size_t)c * HWTOK + (gh * 2) * 64 + gw * 2;
    g_pooledT[(size_t)c * (BATCH * GWIN) + bg] = 0.25f * (p[0] + p[1] + p[64] + p[65]);
}

// ---------------- SGEMM, A accessed transposed (A[k*lda+m]), C row-major ----------------
// 128x128 tile, BK=8, 256 threads, 8x8 register tile per thread.
__global__ __launch_bounds__(256) void sgemm_tn(
    const float* __restrict__ A, int lda, size_t aBatch,
    const float* __restrict__ B1, int ldb1,
    const float* __restrict__ B2, int ldb2, int nsplit,
    int K, float* __restrict__ C, int ldc, size_t cBatch)
{
    __shared__ float As[8][128];
    __shared__ float Bs[8][128];
    const float* Ab = A + (size_t)blockIdx.z * aBatch;
    float*       Cb = C + (size_t)blockIdx.z * cBatch;
    int n0 = blockIdx.x * 128, m0 = blockIdx.y * 128;
    const float* Bw; int ldb, nb;
    if (n0 < nsplit) { Bw = B1; ldb = ldb1; nb = n0; }
    else             { Bw = B2; ldb = ldb2; nb = n0 - nsplit; }
    int tid = threadIdx.x, tx = tid & 15, ty = tid >> 4;

    float acc[8][8];
#pragma unroll
    for (int i = 0; i < 8; i++)
#pragma unroll
        for (int j = 0; j < 8; j++) acc[i][j] = 0.f;

    for (int k0 = 0; k0 < K; k0 += 8) {
#pragma unroll
        for (int t = 0; t < 4; t++) {
            int idx = tid + t * 256;
            int kk = idx >> 7, mm = idx & 127;
            As[kk][mm] = Ab[(size_t)(k0 + kk) * lda + m0 + mm];
            Bs[kk][mm] = Bw[(size_t)(k0 + kk) * ldb + nb + mm];
        }
        __syncthreads();
#pragma unroll
        for (int k = 0; k < 8; k++) {
            float4 a0 = *(const float4*)&As[k][ty * 4];
            float4 a1 = *(const float4*)&As[k][64 + ty * 4];
            float4 b0 = *(const float4*)&Bs[k][tx * 4];
            float4 b1 = *(const float4*)&Bs[k][64 + tx * 4];
            float av[8] = {a0.x, a0.y, a0.z, a0.w, a1.x, a1.y, a1.z, a1.w};
            float bv[8] = {b0.x, b0.y, b0.z, b0.w, b1.x, b1.y, b1.z, b1.w};
#pragma unroll
            for (int i = 0; i < 8; i++)
#pragma unroll
                for (int j = 0; j < 8; j++)
                    acc[i][j] += av[i] * bv[j];
        }
        __syncthreads();
    }
#pragma unroll
    for (int i = 0; i < 8; i++) {
        int m = m0 + ((i < 4) ? (ty * 4 + i) : (64 + ty * 4 + i - 4));
        float4 v0 = make_float4(acc[i][0], acc[i][1], acc[i][2], acc[i][3]);
        float4 v1 = make_float4(acc[i][4], acc[i][5], acc[i][6], acc[i][7]);
        *(float4*)&Cb[(size_t)m * ldc + n0 + tx * 4]      = v0;
        *(float4*)&Cb[(size_t)m * ldc + n0 + 64 + tx * 4] = v1;
    }
}

// ---------------- SGEMM, A row-major (M=16384,K=256), +bias, store transposed to d_out ----------------
__global__ __launch_bounds__(256) void sgemm_proj(
    const float* __restrict__ A, const float* __restrict__ Bw,
    const float* __restrict__ bias, float* __restrict__ out, int cOff)
{
    __shared__ float As[8][128];
    __shared__ float Bs[8][128];
    int n0 = blockIdx.x * 128, m0 = blockIdx.y * 128;
    int tid = threadIdx.x, tx = tid & 15, ty = tid >> 4;

    float acc[8][8];
#pragma unroll
    for (int i = 0; i < 8; i++)
#pragma unroll
        for (int j = 0; j < 8; j++) acc[i][j] = 0.f;

    for (int k0 = 0; k0 < 256; k0 += 8) {
        {   // A tile: 128 rows x 8 k (float4 per half-row-pair)
            int m  = tid >> 1;
            int kq = (tid & 1) * 4;
            float4 av = *(const float4*)&A[(size_t)(m0 + m) * 256 + k0 + kq];
            As[kq + 0][m] = av.x; As[kq + 1][m] = av.y;
            As[kq + 2][m] = av.z; As[kq + 3][m] = av.w;
        }
#pragma unroll
        for (int t = 0; t < 4; t++) {
            int idx = tid + t * 256;
            int kk = idx >> 7, nn = idx & 127;
            Bs[kk][nn] = Bw[(size_t)(k0 + kk) * 256 + n0 + nn];
        }
        __syncthreads();
#pragma unroll
        for (int k = 0; k < 8; k++) {
            float4 a0 = *(const float4*)&As[k][ty * 4];
            float4 a1 = *(const float4*)&As[k][64 + ty * 4];
            float4 b0 = *(const float4*)&Bs[k][tx * 4];
            float4 b1 = *(const float4*)&Bs[k][64 + tx * 4];
            float av[8] = {a0.x, a0.y, a0.z, a0.w, a1.x, a1.y, a1.z, a1.w};
            float bv[8] = {b0.x, b0.y, b0.z, b0.w, b1.x, b1.y, b1.z, b1.w};
#pragma unroll
            for (int i = 0; i < 8; i++)
#pragma unroll
                for (int j = 0; j < 8; j++)
                    acc[i][j] += av[i] * bv[j];
        }
        __syncthreads();
    }
    // store transposed into (B, 512, H, W) layout with bias
#pragma unroll
    for (int j = 0; j < 8; j++) {
        int n = n0 + ((j < 4) ? (tx * 4 + j) : (64 + tx * 4 + j - 4));
        float bv = bias[n];
#pragma unroll
        for (int i = 0; i < 8; i++) {
            int m = m0 + ((i < 4) ? (ty * 4 + i) : (64 + ty * 4 + i - 4));
            int b = m >> 12;
            int token = m & 4095;
            out[(size_t)b * (512 * HWTOK) + (size_t)(cOff + n) * HWTOK + token] = acc[i][j] + bv;
        }
    }
}

// ---------------- hi-fi window attention: one warp per (b, window, head) ----------------
__global__ __launch_bounds__(128) void hi_attn_kernel()
{
    int wgl  = blockIdx.x * 4 + (threadIdx.x >> 5);
    int lane = threadIdx.x & 31;
    int b    = wgl >> 12;
    int rem  = wgl & 4095;
    int g    = rem >> 2;
    int head = rem & 3;
    int gh = g >> 5, gw = g & 31;

    float2 q[4], k[4], v[4];
    int tok[4];
#pragma unroll
    for (int n = 0; n < 4; n++) {
        int hh = gh * 2 + (n >> 1);
        int ww = gw * 2 + (n & 1);
        tok[n] = hh * 64 + ww;
        const float* base = g_qkvq + (size_t)(b * HWTOK + tok[n]) * 1024 + head * 64 + lane * 2;
        q[n] = *(const float2*)(base);
        k[n] = *(const float2*)(base + 256);
        v[n] = *(const float2*)(base + 512);
    }
    float s[4][4];
#pragma unroll
    for (int i = 0; i < 4; i++)
#pragma unroll
        for (int j = 0; j < 4; j++)
            s[i][j] = q[i].x * k[j].x + q[i].y * k[j].y;
#pragma unroll
    for (int off = 16; off; off >>= 1)
#pragma unroll
        for (int i = 0; i < 4; i++)
#pragma unroll
            for (int j = 0; j < 4; j++)
                s[i][j] += __shfl_xor_sync(0xffffffffu, s[i][j], off);

#pragma unroll
    for (int i = 0; i < 4; i++) {
        float s0 = s[i][0] * ATT_SCALE, s1 = s[i][1] * ATT_SCALE;
        float s2 = s[i][2] * ATT_SCALE, s3 = s[i][3] * ATT_SCALE;
        float mx = fmaxf(fmaxf(s0, s1), fmaxf(s2, s3));
        float p0 = __expf(s0 - mx), p1 = __expf(s1 - mx);
        float p2 = __expf(s2 - mx), p3 = __expf(s3 - mx);
        float inv = 1.f / (p0 + p1 + p2 + p3);
        float ox = (p0 * v[0].x + p1 * v[1].x + p2 * v[2].x + p3 * v[3].x) * inv;
        float oy = (p0 * v[0].y + p1 * v[1].y + p2 * v[2].y + p3 * v[3].y) * inv;
        *(float2*)&g_hiat[(size_t)(b * HWTOK + tok[i]) * HDIM + head * 64 + lane * 2] = make_float2(ox, oy);
    }
}

// ---------------- lo-fi attention: flash-style, 64q x 32kv tiles ----------------
__global__ __launch_bounds__(256) void lo_attn_kernel()
{
    __shared__ float QsT[64][65];   // [d][r]
    __shared__ float KsT[64][33];   // [d][kk]
    __shared__ float Vs[32][65];    // [kk][d]
    __shared__ float Ps[64][33];    // [r][kk]
    __shared__ float row_m[64];
    __shared__ float row_l[64];

    int bh = blockIdx.y;
    int b = bh >> 2, head = bh & 3;
    int q0 = blockIdx.x * 64;
    int tid = threadIdx.x, tx = tid & 15, ty = tid >> 4;

#pragma unroll
    for (int t = 0; t < 16; t++) {
        int idx = tid + t * 256;
        int r = idx >> 6, d = idx & 63;
        QsT[d][r] = g_qkvq[(size_t)(b * HWTOK + q0 + r) * 1024 + 768 + head * 64 + d];
    }
    if (tid < 64) { row_m[tid] = -1e30f; row_l[tid] = 0.f; }

    float acc[4][4];
#pragma unroll
    for (int i = 0; i < 4; i++)
#pragma unroll
        for (int j = 0; j < 4; j++) acc[i][j] = 0.f;

    for (int kt = 0; kt < 32; kt++) {
        int kb = kt * 32;
#pragma unroll
        for (int t = 0; t < 8; t++) {
            int idx = tid + t * 256;
            int kk = idx >> 6, d = idx & 63;
            size_t base = (size_t)(b * GWIN + kb + kk) * 512 + head * 64 + d;
            KsT[d][kk] = g_lkv[base];
            Vs[kk][d]  = g_lkv[base + 256];
        }
        __syncthreads();

        float s[4][2] = {{0.f, 0.f}, {0.f, 0.f}, {0.f, 0.f}, {0.f, 0.f}};
#pragma unroll
        for (int d = 0; d < 64; d++) {
            float qa0 = QsT[d][ty * 4 + 0];
            float qa1 = QsT[d][ty * 4 + 1];
            float qa2 = QsT[d][ty * 4 + 2];
            float qa3 = QsT[d][ty * 4 + 3];
            float kb0 = KsT[d][tx * 2 + 0];
            float kb1 = KsT[d][tx * 2 + 1];
            s[0][0] += qa0 * kb0; s[0][1] += qa0 * kb1;
            s[1][0] += qa1 * kb0; s[1][1] += qa1 * kb1;
            s[2][0] += qa2 * kb0; s[2][1] += qa2 * kb1;
            s[3][0] += qa3 * kb0; s[3][1] += qa3 * kb1;
        }
#pragma unroll
        for (int i = 0; i < 4; i++) { s[i][0] *= ATT_SCALE; s[i][1] *= ATT_SCALE; }

        float pm[4], psum[4], mnew[4], fac[4];
#pragma unroll
        for (int i = 0; i < 4; i++) pm[i] = fmaxf(s[i][0], s[i][1]);
#pragma unroll
        for (int off = 8; off; off >>= 1)
#pragma unroll
            for (int i = 0; i < 4; i++)
                pm[i] = fmaxf(pm[i], __shfl_xor_sync(0xffffffffu, pm[i], off));
#pragma unroll
        for (int i = 0; i < 4; i++) {
            float mp = row_m[ty * 4 + i];
            mnew[i] = fmaxf(mp, pm[i]);
            fac[i]  = __expf(mp - mnew[i]);
        }
#pragma unroll
        for (int i = 0; i < 4; i++) {
            float p0 = __expf(s[i][0] - mnew[i]);
            float p1 = __expf(s[i][1] - mnew[i]);
            Ps[ty * 4 + i][tx * 2 + 0] = p0;
            Ps[ty * 4 + i][tx * 2 + 1] = p1;
            psum[i] = p0 + p1;
        }
#pragma unroll
        for (int off = 8; off; off >>= 1)
#pragma unroll
            for (int i = 0; i < 4; i++)
                psum[i] += __shfl_xor_sync(0xffffffffu, psum[i], off);
        __syncwarp();
        if (tx == 0) {
#pragma unroll
            for (int i = 0; i < 4; i++) {
                row_m[ty * 4 + i] = mnew[i];
                row_l[ty * 4 + i] = row_l[ty * 4 + i] * fac[i] + psum[i];
            }
        }
#pragma unroll
        for (int i = 0; i < 4; i++)
#pragma unroll
            for (int j = 0; j < 4; j++)
                acc[i][j] *= fac[i];
        __syncthreads();   // Ps + row stats visible

#pragma unroll
        for (int kk = 0; kk < 32; kk++) {
            float p0 = Ps[ty * 4 + 0][kk];
            float p1 = Ps[ty * 4 + 1][kk];
            float p2 = Ps[ty * 4 + 2][kk];
            float p3 = Ps[ty * 4 + 3][kk];
            float v0 = Vs[kk][tx * 4 + 0];
            float v1 = Vs[kk][tx * 4 + 1];
            float v2 = Vs[kk][tx * 4 + 2];
            float v3 = Vs[kk][tx * 4 + 3];
            acc[0][0] += p0 * v0; acc[0][1] += p0 * v1; acc[0][2] += p0 * v2; acc[0][3] += p0 * v3;
            acc[1][0] += p1 * v0; acc[1][1] += p1 * v1; acc[1][2] += p1 * v2; acc[1][3] += p1 * v3;
            acc[2][0] += p2 * v0; acc[2][1] += p2 * v1; acc[2][2] += p2 * v2; acc[2][3] += p2 * v3;
            acc[3][0] += p3 * v0; acc[3][1] += p3 * v1; acc[3][2] += p3 * v2; acc[3][3] += p3 * v3;
        }
        __syncthreads();   // done with KsT/Vs/Ps before next tile load
    }

#pragma unroll
    for (int i = 0; i < 4; i++) {
        float invl = 1.0f / row_l[ty * 4 + i];
        float4 v = make_float4(acc[i][0] * invl, acc[i][1] * invl, acc[i][2] * invl, acc[i][3] * invl);
        *(float4*)&g_loat[(size_t)(b * HWTOK + q0 + ty * 4 + i) * LDIM + head * 64 + tx * 4] = v;
    }
}

// ---------------- launch ----------------
extern "C" void kernel_launch(void* const* d_in, const int* in_sizes, int n_in,
                              void* d_out, int out_size)
{
    (void)in_sizes; (void)n_in; (void)out_size;
    const float* x        = (const float*)d_in[0];
    const float* h_qkv_w  = (const float*)d_in[1];
    const float* h_proj_w = (const float*)d_in[2];
    const float* h_proj_b = (const float*)d_in[3];
    const float* l_q_w    = (const float*)d_in[4];
    const float* l_kv_w   = (const float*)d_in[5];
    const float* l_proj_w = (const float*)d_in[6];
    const float* l_proj_b = (const float*)d_in[7];
    float* out = (float*)d_out;

    float *pooledT, *qkvq, *lkv, *hiat, *loat;
    cudaGetSymbolAddress((void**)&pooledT, g_pooledT);
    cudaGetSymbolAddress((void**)&qkvq,    g_qkvq);
    cudaGetSymbolAddress((void**)&lkv,     g_lkv);
    cudaGetSymbolAddress((void**)&hiat,    g_hiat);
    cudaGetSymbolAddress((void**)&loat,    g_loat);

    // 1. window pooling (for lo-fi kv)
    pool_kernel<<<(CDIM * BATCH * GWIN) / 256, 256>>>(x);

    // 2. fused qkv_hi | q_lo GEMM: per batch, (4096 x 512) @ (512 x 1024)
    sgemm_tn<<<dim3(8, 32, 4), 256>>>(
        x, HWTOK, (size_t)CDIM * HWTOK,
        h_qkv_w, 768, l_q_w, 256, 768,
        CDIM, qkvq, 1024, (size_t)HWTOK * 1024);

    // 3. lo-fi kv GEMM: (4096 x 512) @ (512 x 512)
    sgemm_tn<<<dim3(4, 32, 1), 256>>>(
        pooledT, BATCH * GWIN, 0,
        l_kv_w, 512, l_kv_w, 512, 1 << 30,
        CDIM, lkv, 512, 0);

    // 4. hi-fi window attention
    hi_attn_kernel<<<4096, 128>>>();

    // 5. hi-fi projection -> out channels [0,256)
    sgemm_proj<<<dim3(2, 128), 256>>>(hiat, h_proj_w, h_proj_b, out, 0);

    // 6. lo-fi attention
    lo_attn_kernel<<<dim3(64, 16), 256>>>();

    // 7. lo-fi projection -> out channels [256,512)
    sgemm_proj<<<dim3(2, 128), 256>>>(loat, l_proj_w, l_proj_b, out, 256);
}

// round 3
// speedup vs baseline: 2.5699x; 2.5699x over previous
#include <cuda_runtime.h>
#include <math.h>
#include <stdint.h>

// ---------------- problem constants ----------------
#define BATCH   4
#define CDIM    512
#define HWTOK   4096          // 64*64
#define GWIN    1024          // 32*32 windows per batch
#define HDIM    256
#define LDIM    256
#define ATT_SCALE 0.125f      // 64^-0.5

#define LDT 132               // padded row (floats) for 128-wide smem tiles

// ---------------- scratch (device globals; no allocation allowed) ----------------
__device__ float g_pooledT[CDIM * (BATCH * GWIN)];            // [c][b*G+g]
__device__ float g_qkvq[(size_t)BATCH * HWTOK * 1024];        // [tok][qkv_hi 768 | q_lo 256]
__device__ float g_lkv[BATCH * GWIN * 512];                   // [b*G+g][k 256 | v 256]
__device__ float g_hiat[(size_t)BATCH * HWTOK * HDIM];        // hi attention out
__device__ float g_loat[(size_t)BATCH * HWTOK * LDIM];        // lo attention out

// ---------------- tf32 helpers ----------------
__device__ __forceinline__ float to_tf32(float x) {
    uint32_t r;
    asm("cvt.rna.tf32.f32 %0, %1;" : "=r"(r) : "f"(x));
    return __uint_as_float(r);
}
__device__ __forceinline__ float4 to_tf32_4(float4 v) {
    v.x = to_tf32(v.x); v.y = to_tf32(v.y); v.z = to_tf32(v.z); v.w = to_tf32(v.w);
    return v;
}
// D = A(16x8) * B(8x8) + D, tf32 in, f32 out.
// a0:(g,tig) a1:(g+8,tig) a2:(g,tig+4) a3:(g+8,tig+4)
// b0:(k=tig,n=g) b1:(k=tig+4,n=g)
// c0:(g,2tig) c1:(g,2tig+1) c2:(g+8,2tig) c3:(g+8,2tig+1)
__device__ __forceinline__ void mma_tf32(float4& c, const uint32_t* a, const uint32_t* b) {
    asm volatile(
        "mma.sync.aligned.m16n8k8.row.col.f32.tf32.tf32.f32 "
        "{%0,%1,%2,%3}, {%4,%5,%6,%7}, {%8,%9}, {%0,%1,%2,%3};\n"
        : "+f"(c.x), "+f"(c.y), "+f"(c.z), "+f"(c.w)
        : "r"(a[0]), "r"(a[1]), "r"(a[2]), "r"(a[3]), "r"(b[0]), "r"(b[1]));
}

// ---------------- kernel 1: window pooling (mean of 2x2), stored transposed ----------------
__global__ void pool_kernel(const float* __restrict__ x)
{
    int idx = blockIdx.x * blockDim.x + threadIdx.x;
    if (idx >= CDIM * BATCH * GWIN) return;
    int bg = idx & 4095;
    int c  = idx >> 12;
    int b  = bg >> 10;
    int g  = bg & 1023;
    int gh = g >> 5, gw = g & 31;
    const float* p = x + (size_t)b * CDIM * HWTOK + (size_t)c * HWTOK + (gh * 2) * 64 + gw * 2;
    g_pooledT[(size_t)c * (BATCH * GWIN) + bg] = 0.25f * (p[0] + p[1] + p[64] + p[65]);
}

// ---------------- tf32 GEMM: A K-major (A[k*lda+m]), B row-major, C row-major ----------------
// 128x128 block tile, K-slab 16, 256 threads = 8 warps (2m x 4n), warp tile 64x32.
__global__ __launch_bounds__(256) void gemm_tf32(
    const float* __restrict__ A, int lda, size_t aBatch,
    const float* __restrict__ B1, int ldb1,
    const float* __restrict__ B2, int ldb2, int nsplit,
    int K, float* __restrict__ C, int ldc, size_t cBatch)
{
    __shared__ float As[16 * LDT];
    __shared__ float Bs[16 * LDT];
    const float* Ab = A + (size_t)blockIdx.z * aBatch;
    float*       Cb = C + (size_t)blockIdx.z * cBatch;
    int n0 = blockIdx.x * 128, m0 = blockIdx.y * 128;
    const float* Bw; int ldb, nb;
    if (n0 < nsplit) { Bw = B1; ldb = ldb1; nb = n0; }
    else             { Bw = B2; ldb = ldb2; nb = n0 - nsplit; }

    int tid  = threadIdx.x;
    int lane = tid & 31, wid = tid >> 5;
    int g = lane >> 2, tig = lane & 3;
    int wm0 = (wid & 1) * 64;        // warp m offset
    int wn0 = (wid >> 1) * 32;       // warp n offset

    float4 acc[4][4];
#pragma unroll
    for (int i = 0; i < 4; i++)
#pragma unroll
        for (int j = 0; j < 4; j++) acc[i][j] = make_float4(0.f, 0.f, 0.f, 0.f);

#pragma unroll 1
    for (int k0 = 0; k0 < K; k0 += 16) {
        // stage A/B slabs (16 x 128) as tf32
#pragma unroll
        for (int i = 0; i < 2; i++) {
            int f  = tid + i * 256;           // 512 float4 per tensor
            int kk = f >> 5, mm = (f & 31) * 4;
            float4 av = *(const float4*)&Ab[(size_t)(k0 + kk) * lda + m0 + mm];
            float4 bv = *(const float4*)&Bw[(size_t)(k0 + kk) * ldb + nb + mm];
            *(float4*)&As[kk * LDT + mm] = to_tf32_4(av);
            *(float4*)&Bs[kk * LDT + mm] = to_tf32_4(bv);
        }
        __syncthreads();

#pragma unroll
        for (int ks = 0; ks < 16; ks += 8) {
            uint32_t a[4][4], b[4][2];
#pragma unroll
            for (int mf = 0; mf < 4; mf++) {
                int r = wm0 + mf * 16 + g;
                a[mf][0] = __float_as_uint(As[(ks + tig) * LDT + r]);
                a[mf][1] = __float_as_uint(As[(ks + tig) * LDT + r + 8]);
                a[mf][2] = __float_as_uint(As[(ks + tig + 4) * LDT + r]);
                a[mf][3] = __float_as_uint(As[(ks + tig + 4) * LDT + r + 8]);
            }
#pragma unroll
            for (int nf = 0; nf < 4; nf++) {
                int c = wn0 + nf * 8 + g;
                b[nf][0] = __float_as_uint(Bs[(ks + tig) * LDT + c]);
                b[nf][1] = __float_as_uint(Bs[(ks + tig + 4) * LDT + c]);
            }
#pragma unroll
            for (int mf = 0; mf < 4; mf++)
#pragma unroll
                for (int nf = 0; nf < 4; nf++)
                    mma_tf32(acc[mf][nf], a[mf], b[nf]);
        }
        __syncthreads();
    }

#pragma unroll
    for (int mf = 0; mf < 4; mf++) {
        int row = m0 + wm0 + mf * 16 + g;
#pragma unroll
        for (int nf = 0; nf < 4; nf++) {
            int col = n0 + wn0 + nf * 8 + 2 * tig;
            *(float2*)&Cb[(size_t)row * ldc + col]       = make_float2(acc[mf][nf].x, acc[mf][nf].y);
            *(float2*)&Cb[(size_t)(row + 8) * ldc + col] = make_float2(acc[mf][nf].z, acc[mf][nf].w);
        }
    }
}

// ---------------- tf32 projection GEMM: A row-major [M,256], +bias, transposed store ----------------
__global__ __launch_bounds__(256) void proj_tf32(
    const float* __restrict__ A, const float* __restrict__ Bw,
    const float* __restrict__ bias, float* __restrict__ out, int cOff)
{
    __shared__ float As[16 * LDT];
    __shared__ float Bs[16 * LDT];
    int n0 = blockIdx.x * 128, m0 = blockIdx.y * 128;
    int tid  = threadIdx.x;
    int lane = tid & 31, wid = tid >> 5;
    int g = lane >> 2, tig = lane & 3;
    int wm0 = (wid & 1) * 64;
    int wn0 = (wid >> 1) * 32;

    float4 acc[4][4];
#pragma unroll
    for (int i = 0; i < 4; i++)
#pragma unroll
        for (int j = 0; j < 4; j++) acc[i][j] = make_float4(0.f, 0.f, 0.f, 0.f);

#pragma unroll 1
    for (int k0 = 0; k0 < 256; k0 += 16) {
#pragma unroll
        for (int i = 0; i < 2; i++) {
            int f = tid + i * 256;
            // A: 128 rows x 16 k, row-major in gmem -> transpose into As[k][m]
            int mm = f >> 2, kq = (f & 3) * 4;
            float4 av = to_tf32_4(*(const float4*)&A[(size_t)(m0 + mm) * 256 + k0 + kq]);
            As[(kq + 0) * LDT + mm] = av.x;
            As[(kq + 1) * LDT + mm] = av.y;
            As[(kq + 2) * LDT + mm] = av.z;
            As[(kq + 3) * LDT + mm] = av.w;
            // B: row-major [k][n]
            int kk = f >> 5, nn = (f & 31) * 4;
            float4 bv = to_tf32_4(*(const float4*)&Bw[(size_t)(k0 + kk) * 256 + n0 + nn]);
            *(float4*)&Bs[kk * LDT + nn] = bv;
        }
        __syncthreads();

#pragma unroll
        for (int ks = 0; ks < 16; ks += 8) {
            uint32_t a[4][4], b[4][2];
#pragma unroll
            for (int mf = 0; mf < 4; mf++) {
                int r = wm0 + mf * 16 + g;
                a[mf][0] = __float_as_uint(As[(ks + tig) * LDT + r]);
                a[mf][1] = __float_as_uint(As[(ks + tig) * LDT + r + 8]);
                a[mf][2] = __float_as_uint(As[(ks + tig + 4) * LDT + r]);
                a[mf][3] = __float_as_uint(As[(ks + tig + 4) * LDT + r + 8]);
            }
#pragma unroll
            for (int nf = 0; nf < 4; nf++) {
                int c = wn0 + nf * 8 + g;
                b[nf][0] = __float_as_uint(Bs[(ks + tig) * LDT + c]);
                b[nf][1] = __float_as_uint(Bs[(ks + tig + 4) * LDT + c]);
            }
#pragma unroll
            for (int mf = 0; mf < 4; mf++)
#pragma unroll
                for (int nf = 0; nf < 4; nf++)
                    mma_tf32(acc[mf][nf], a[mf], b[nf]);
        }
        __syncthreads();
    }

    // store transposed into (B, 512, 64, 64) with bias
#pragma unroll
    for (int nf = 0; nf < 4; nf++) {
        int n  = wn0 + nf * 8 + 2 * tig;
        float bv0 = bias[n0 + n], bv1 = bias[n0 + n + 1];
        size_t ch0 = (size_t)(cOff + n0 + n) * HWTOK;
#pragma unroll
        for (int mf = 0; mf < 4; mf++) {
            int m = m0 + wm0 + mf * 16 + g;
            int b0i = m >> 12, tok0 = m & 4095;
            int b1i = (m + 8) >> 12, tok1 = (m + 8) & 4095;
            size_t base0 = (size_t)b0i * (512 * HWTOK);
            size_t base1 = (size_t)b1i * (512 * HWTOK);
            out[base0 + ch0 + tok0]         = acc[mf][nf].x + bv0;
            out[base0 + ch0 + HWTOK + tok0] = acc[mf][nf].y + bv1;
            out[base1 + ch0 + tok1]         = acc[mf][nf].z + bv0;
            out[base1 + ch0 + HWTOK + tok1] = acc[mf][nf].w + bv1;
        }
    }
}

// ---------------- hi-fi window attention: one warp per (b, window, head) ----------------
__global__ __launch_bounds__(128) void hi_attn_kernel()
{
    int wgl  = blockIdx.x * 4 + (threadIdx.x >> 5);
    int lane = threadIdx.x & 31;
    int b    = wgl >> 12;
    int rem  = wgl & 4095;
    int g    = rem >> 2;
    int head = rem & 3;
    int gh = g >> 5, gw = g & 31;

    float2 q[4], k[4], v[4];
    int tok[4];
#pragma unroll
    for (int n = 0; n < 4; n++) {
        int hh = gh * 2 + (n >> 1);
        int ww = gw * 2 + (n & 1);
        tok[n] = hh * 64 + ww;
        const float* base = g_qkvq + (size_t)(b * HWTOK + tok[n]) * 1024 + head * 64 + lane * 2;
        q[n] = *(const float2*)(base);
        k[n] = *(const float2*)(base + 256);
        v[n] = *(const float2*)(base + 512);
    }
    float s[4][4];
#pragma unroll
    for (int i = 0; i < 4; i++)
#pragma unroll
        for (int j = 0; j < 4; j++)
            s[i][j] = q[i].x * k[j].x + q[i].y * k[j].y;
#pragma unroll
    for (int off = 16; off; off >>= 1)
#pragma unroll
        for (int i = 0; i < 4; i++)
#pragma unroll
            for (int j = 0; j < 4; j++)
                s[i][j] += __shfl_xor_sync(0xffffffffu, s[i][j], off);

#pragma unroll
    for (int i = 0; i < 4; i++) {
        float s0 = s[i][0] * ATT_SCALE, s1 = s[i][1] * ATT_SCALE;
        float s2 = s[i][2] * ATT_SCALE, s3 = s[i][3] * ATT_SCALE;
        float mx = fmaxf(fmaxf(s0, s1), fmaxf(s2, s3));
        float p0 = __expf(s0 - mx), p1 = __expf(s1 - mx);
        float p2 = __expf(s2 - mx), p3 = __expf(s3 - mx);
        float inv = 1.f / (p0 + p1 + p2 + p3);
        float ox = (p0 * v[0].x + p1 * v[1].x + p2 * v[2].x + p3 * v[3].x) * inv;
        float oy = (p0 * v[0].y + p1 * v[1].y + p2 * v[2].y + p3 * v[3].y) * inv;
        *(float2*)&g_hiat[(size_t)(b * HWTOK + tok[i]) * HDIM + head * 64 + lane * 2] = make_float2(ox, oy);
    }
}

// ---------------- lo-fi attention: flash-style with tf32 mma ----------------
// block = 256 threads = 8 warps; q tile 128 rows (16/warp); kv chunks of 64.
// dyn smem: Ks 64x68 | Vs 64x68 | Ps 128x68 (also Q staging) floats.
#define LDK 68
#define LO_SMEM ((64 * LDK * 2 + 128 * LDK) * 4)

__global__ __launch_bounds__(256) void lo_attn_mma()
{
    extern __shared__ float sm[];
    float* Ks = sm;
    float* Vs = sm + 64 * LDK;
    float* Ps = sm + 2 * 64 * LDK;

    int bh = blockIdx.y;
    int b = bh >> 2, head = bh & 3;
    int q0 = blockIdx.x * 128;
    int tid  = threadIdx.x;
    int lane = tid & 31, wid = tid >> 5;
    int g = lane >> 2, tig = lane & 3;
    int rr = wid * 16 + g;           // this thread's low q-row within tile

    // ---- stage Q tile (128 x 64) into Ps, then load register A-fragments ----
#pragma unroll
    for (int i = 0; i < 8; i++) {
        int f = tid + i * 256;       // 2048 float4
        int r = f >> 4, dq = (f & 15) * 4;
        float4 qv = *(const float4*)&g_qkvq[(size_t)(b * HWTOK + q0 + r) * 1024 + 768 + head * 64 + dq];
        *(float4*)&Ps[r * LDK + dq] = to_tf32_4(qv);
    }
    __syncthreads();
    uint32_t qa[8][4];
#pragma unroll
    for (int kf = 0; kf < 8; kf++) {
        qa[kf][0] = __float_as_uint(Ps[rr * LDK + kf * 8 + tig]);
        qa[kf][1] = __float_as_uint(Ps[(rr + 8) * LDK + kf * 8 + tig]);
        qa[kf][2] = __float_as_uint(Ps[rr * LDK + kf * 8 + tig + 4]);
        qa[kf][3] = __float_as_uint(Ps[(rr + 8) * LDK + kf * 8 + tig + 4]);
    }

    float4 o[8];
#pragma unroll
    for (int nf = 0; nf < 8; nf++) o[nf] = make_float4(0.f, 0.f, 0.f, 0.f);
    float m_lo = -1e30f, m_hi = -1e30f, l_lo = 0.f, l_hi = 0.f;

    __syncthreads();

    for (int ch = 0; ch < 16; ch++) {
        // ---- load K/V chunk (64 x 64 each) ----
#pragma unroll
        for (int i = 0; i < 4; i++) {
            int f = tid + i * 256;   // 1024 float4 per tensor
            int r = f >> 4, dq = (f & 15) * 4;
            size_t base = (size_t)(b * GWIN + ch * 64 + r) * 512 + head * 64 + dq;
            *(float4*)&Ks[r * LDK + dq] = to_tf32_4(*(const float4*)&g_lkv[base]);
            *(float4*)&Vs[r * LDK + dq] = to_tf32_4(*(const float4*)&g_lkv[base + 256]);
        }
        __syncthreads();

        // ---- S = Q @ K^T (m16 x n64 per warp) ----
        float4 s[8];
#pragma unroll
        for (int nf = 0; nf < 8; nf++) s[nf] = make_float4(0.f, 0.f, 0.f, 0.f);
#pragma unroll
        for (int kf = 0; kf < 8; kf++) {
#pragma unroll
            for (int nf = 0; nf < 8; nf++) {
                uint32_t bb[2];
                bb[0] = __float_as_uint(Ks[(nf * 8 + g) * LDK + kf * 8 + tig]);
                bb[1] = __float_as_uint(Ks[(nf * 8 + g) * LDK + kf * 8 + tig + 4]);
                mma_tf32(s[nf], qa[kf], bb);
            }
        }

        // ---- online softmax on C fragments ----
        float mx_lo = -1e30f, mx_hi = -1e30f;
#pragma unroll
        for (int nf = 0; nf < 8; nf++) {
            s[nf].x *= ATT_SCALE; s[nf].y *= ATT_SCALE;
            s[nf].z *= ATT_SCALE; s[nf].w *= ATT_SCALE;
            mx_lo = fmaxf(mx_lo, fmaxf(s[nf].x, s[nf].y));
            mx_hi = fmaxf(mx_hi, fmaxf(s[nf].z, s[nf].w));
        }
        mx_lo = fmaxf(mx_lo, __shfl_xor_sync(0xffffffffu, mx_lo, 1));
        mx_lo = fmaxf(mx_lo, __shfl_xor_sync(0xffffffffu, mx_lo, 2));
        mx_hi = fmaxf(mx_hi, __shfl_xor_sync(0xffffffffu, mx_hi, 1));
        mx_hi = fmaxf(mx_hi, __shfl_xor_sync(0xffffffffu, mx_hi, 2));

        float mn_lo = fmaxf(m_lo, mx_lo);
        float mn_hi = fmaxf(m_hi, mx_hi);
        float fac_lo = __expf(m_lo - mn_lo);
        float fac_hi = __expf(m_hi - mn_hi);
        m_lo = mn_lo; m_hi = mn_hi;

        float sum_lo = 0.f, sum_hi = 0.f;
#pragma unroll
        for (int nf = 0; nf < 8; nf++) {
            float p0 = __expf(s[nf].x - mn_lo);
            float p1 = __expf(s[nf].y - mn_lo);
            float p2 = __expf(s[nf].z - mn_hi);
            float p3 = __expf(s[nf].w - mn_hi);
            sum_lo += p0 + p1; sum_hi += p2 + p3;
            int col = nf * 8 + 2 * tig;
            *(float2*)&Ps[rr * LDK + col]       = make_float2(to_tf32(p0), to_tf32(p1));
            *(float2*)&Ps[(rr + 8) * LDK + col] = make_float2(to_tf32(p2), to_tf32(p3));
        }
        sum_lo += __shfl_xor_sync(0xffffffffu, sum_lo, 1);
        sum_lo += __shfl_xor_sync(0xffffffffu, sum_lo, 2);
        sum_hi += __shfl_xor_sync(0xffffffffu, sum_hi, 1);
        sum_hi += __shfl_xor_sync(0xffffffffu, sum_hi, 2);
        l_lo = l_lo * fac_lo + sum_lo;
        l_hi = l_hi * fac_hi + sum_hi;

#pragma unroll
        for (int nf = 0; nf < 8; nf++) {
            o[nf].x *= fac_lo; o[nf].y *= fac_lo;
            o[nf].z *= fac_hi; o[nf].w *= fac_hi;
        }
        __syncwarp();   // Ps (warp-private rows) visible within warp

        // ---- O += P @ V (m16 x d64 per warp, k = 64 kv) ----
#pragma unroll
        for (int kf = 0; kf < 8; kf++) {
            uint32_t pa[4];
            pa[0] = __float_as_uint(Ps[rr * LDK + kf * 8 + tig]);
            pa[1] = __float_as_uint(Ps[(rr + 8) * LDK + kf * 8 + tig]);
            pa[2] = __float_as_uint(Ps[rr * LDK + kf * 8 + tig + 4]);
            pa[3] = __float_as_uint(Ps[(rr + 8) * LDK + kf * 8 + tig + 4]);
#pragma unroll
            for (int nf = 0; nf < 8; nf++) {
                uint32_t bb[2];
                bb[0] = __float_as_uint(Vs[(kf * 8 + tig) * LDK + nf * 8 + g]);
                bb[1] = __float_as_uint(Vs[(kf * 8 + tig + 4) * LDK + nf * 8 + g]);
                mma_tf32(o[nf], pa, bb);
            }
        }
        __syncthreads();  // all warps done with Ks/Vs before next chunk
    }

    float inv_lo = 1.f / l_lo;
    float inv_hi = 1.f / l_hi;
    size_t row0 = (size_t)(b * HWTOK + q0 + rr);
#pragma unroll
    for (int nf = 0; nf < 8; nf++) {
        int col = head * 64 + nf * 8 + 2 * tig;
        *(float2*)&g_loat[row0 * LDIM + col]       = make_float2(o[nf].x * inv_lo, o[nf].y * inv_lo);
        *(float2*)&g_loat[(row0 + 8) * LDIM + col] = make_float2(o[nf].z * inv_hi, o[nf].w * inv_hi);
    }
}

// ---------------- launch ----------------
extern "C" void kernel_launch(void* const* d_in, const int* in_sizes, int n_in,
                              void* d_out, int out_size)
{
    (void)in_sizes; (void)n_in; (void)out_size;
    const float* x        = (const float*)d_in[0];
    const float* h_qkv_w  = (const float*)d_in[1];
    const float* h_proj_w = (const float*)d_in[2];
    const float* h_proj_b = (const float*)d_in[3];
    const float* l_q_w    = (const float*)d_in[4];
    const float* l_kv_w   = (const float*)d_in[5];
    const float* l_proj_w = (const float*)d_in[6];
    const float* l_proj_b = (const float*)d_in[7];
    float* out = (float*)d_out;

    float *pooledT, *qkvq, *lkv, *hiat, *loat;
    cudaGetSymbolAddress((void**)&pooledT, g_pooledT);
    cudaGetSymbolAddress((void**)&qkvq,    g_qkvq);
    cudaGetSymbolAddress((void**)&lkv,     g_lkv);
    cudaGetSymbolAddress((void**)&hiat,    g_hiat);
    cudaGetSymbolAddress((void**)&loat,    g_loat);

    cudaFuncSetAttribute(lo_attn_mma, cudaFuncAttributeMaxDynamicSharedMemorySize, LO_SMEM);

    // 1. window pooling (for lo-fi kv)
    pool_kernel<<<(CDIM * BATCH * GWIN) / 256, 256>>>(x);

    // 2. fused qkv_hi | q_lo GEMM: per batch (4096 x 512) @ (512 x 1024)
    gemm_tf32<<<dim3(8, 32, 4), 256>>>(
        x, HWTOK, (size_t)CDIM * HWTOK,
        h_qkv_w, 768, l_q_w, 256, 768,
        CDIM, qkvq, 1024, (size_t)HWTOK * 1024);

    // 3. lo-fi kv GEMM: (4096 x 512) @ (512 x 512)
    gemm_tf32<<<dim3(4, 32, 1), 256>>>(
        pooledT, BATCH * GWIN, 0,
        l_kv_w, 512, l_kv_w, 512, 1 << 30,
        CDIM, lkv, 512, 0);

    // 4. hi-fi window attention
    hi_attn_kernel<<<4096, 128>>>();

    // 5. hi-fi projection -> out channels [0,256)
    proj_tf32<<<dim3(2, 128), 256>>>(hiat, h_proj_w, h_proj_b, out, 0);

    // 6. lo-fi attention (tensor-core flash)
    lo_attn_mma<<<dim3(32, 16), 256, LO_SMEM>>>();

    // 7. lo-fi projection -> out channels [256,512)
    proj_tf32<<<dim3(2, 128), 256>>>(loat, l_proj_w, l_proj_b, out, 256);
}

// round 7
// speedup vs baseline: 3.1441x; 1.2235x over previous
#include <cuda_runtime.h>
#include <math.h>
#include <stdint.h>

// ---------------- problem constants ----------------
#define BATCH   4
#define CDIM    512
#define HWTOK   4096          // 64*64
#define GWIN    1024          // 32*32 windows per batch
#define HDIM    256
#define LDIM    256
#define ATT_SCALE 0.125f      // 64^-0.5

#define LDT 132               // padded row (floats) for 128-wide smem tiles
#define LDA2 20               // padded row for proj A tiles (16 + 4)

// weight scratch offsets (floats)
#define W_QKV 0
#define W_LQ  393216
#define W_LKV 524288
#define W_HP  786432
#define W_LP  851968
#define W_TOT 917504

// ---------------- scratch (device globals; no allocation allowed) ----------------
__device__ float g_xr[(size_t)BATCH * CDIM * HWTOK];          // tf32-rounded x
__device__ float g_wr[W_TOT];                                 // tf32-rounded weights
__device__ float g_pooledT[CDIM * (BATCH * GWIN)];            // [c][b*G+g], rounded
__device__ float g_qkvq[(size_t)BATCH * HWTOK * 1024];        // [tok][qkv_hi 768 (fp32) | q_lo 256 (rounded)]
__device__ float g_lkv[BATCH * GWIN * 512];                   // [b*G+g][k|v], rounded
__device__ float g_hiat[(size_t)BATCH * HWTOK * HDIM];        // hi attn out, rounded
__device__ float g_loat[(size_t)BATCH * HWTOK * LDIM];        // lo attn out, rounded

// ---------------- tf32 / cp.async helpers ----------------
__device__ __forceinline__ float to_tf32(float x) {
    uint32_t r;
    asm("cvt.rna.tf32.f32 %0, %1;" : "=r"(r) : "f"(x));
    return __uint_as_float(r);
}
__device__ __forceinline__ float4 to_tf32_4(float4 v) {
    v.x = to_tf32(v.x); v.y = to_tf32(v.y); v.z = to_tf32(v.z); v.w = to_tf32(v.w);
    return v;
}
__device__ __forceinline__ void cp16(void* dst, const void* src) {
    uint32_t d = (uint32_t)__cvta_generic_to_shared(dst);
    asm volatile("cp.async.cg.shared.global [%0], [%1], 16;\n" :: "r"(d), "l"(src) : "memory");
}
#define CP_COMMIT asm volatile("cp.async.commit_group;\n" ::: "memory")
#define CP_WAIT1  asm volatile("cp.async.wait_group 1;\n" ::: "memory")

// D = A(16x8) * B(8x8) + D, tf32 in, f32 out.
__device__ __forceinline__ void mma_tf32(float4& c, const uint32_t* a, const uint32_t* b) {
    asm volatile(
        "mma.sync.aligned.m16n8k8.row.col.f32.tf32.tf32.f32 "
        "{%0,%1,%2,%3}, {%4,%5,%6,%7}, {%8,%9}, {%0,%1,%2,%3};\n"
        : "+f"(c.x), "+f"(c.y), "+f"(c.z), "+f"(c.w)
        : "r"(a[0]), "r"(a[1]), "r"(a[2]), "r"(a[3]), "r"(b[0]), "r"(b[1]));
}

// ---------------- prep: round x and weights to tf32 once ----------------
__global__ void round_x_kernel(const float* __restrict__ x)
{
    int i = blockIdx.x * blockDim.x + threadIdx.x;   // float4 index
    float4 v = ((const float4*)x)[i];
    ((float4*)g_xr)[i] = to_tf32_4(v);
}
__global__ void round_w_kernel(const float* __restrict__ w1, const float* __restrict__ w2,
                               const float* __restrict__ w3, const float* __restrict__ w4,
                               const float* __restrict__ w5)
{
    int i = blockIdx.x * blockDim.x + threadIdx.x;   // float4 index
    int f = i * 4;
    const float* src; int off;
    if      (f < W_LQ)  { src = w1; off = f - W_QKV; }
    else if (f < W_LKV) { src = w2; off = f - W_LQ; }
    else if (f < W_HP)  { src = w3; off = f - W_LKV; }
    else if (f < W_LP)  { src = w4; off = f - W_HP; }
    else                { src = w5; off = f - W_LP; }
    float4 v = *(const float4*)(src + off);
    *(float4*)(g_wr + f) = to_tf32_4(v);
}

// ---------------- window pooling (mean of 2x2), transposed + rounded ----------------
__global__ void pool_kernel(const float* __restrict__ x)
{
    int idx = blockIdx.x * blockDim.x + threadIdx.x;
    if (idx >= CDIM * BATCH * GWIN) return;
    int bg = idx & 4095;
    int c  = idx >> 12;
    int b  = bg >> 10;
    int g  = bg & 1023;
    int gh = g >> 5, gw = g & 31;
    const float* p = x + (size_t)b * CDIM * HWTOK + (size_t)c * HWTOK + (gh * 2) * 64 + gw * 2;
    g_pooledT[(size_t)c * (BATCH * GWIN) + bg] = to_tf32(0.25f * (p[0] + p[1] + p[64] + p[65]));
}

// ---------------- tf32 GEMM, double-buffered cp.async ----------------
// A K-major pre-rounded (A[k*lda+m]), B row-major pre-rounded, C row-major.
// 128x128 tile, K-slab 16, 256 threads = 8 warps (2m x 4n), warp tile 64x32.
__global__ __launch_bounds__(256) void gemm_tf32(
    const float* __restrict__ A, int lda, size_t aBatch,
    const float* __restrict__ B1, int ldb1,
    const float* __restrict__ B2, int ldb2, int nsplit,
    int K, float* __restrict__ C, int ldc, size_t cBatch, int roundCol)
{
    __shared__ float As[2][16 * LDT];
    __shared__ float Bs[2][16 * LDT];
    const float* Ab = A + (size_t)blockIdx.z * aBatch;
    float*       Cb = C + (size_t)blockIdx.z * cBatch;
    int n0 = blockIdx.x * 128, m0 = blockIdx.y * 128;
    const float* Bw; int ldb, nb;
    if (n0 < nsplit) { Bw = B1; ldb = ldb1; nb = n0; }
    else             { Bw = B2; ldb = ldb2; nb = n0 - nsplit; }

    int tid  = threadIdx.x;
    int lane = tid & 31, wid = tid >> 5;
    int g = lane >> 2, tig = lane & 3;
    int wm0 = (wid & 1) * 64;
    int wn0 = (wid >> 1) * 32;
    int kks = tid >> 5;            // staging row (0..7; +8 for 2nd chunk)
    int mms = (tid & 31) * 4;

    float4 acc[4][4];
#pragma unroll
    for (int i = 0; i < 4; i++)
#pragma unroll
        for (int j = 0; j < 4; j++) acc[i][j] = make_float4(0.f, 0.f, 0.f, 0.f);

    int nIter = K >> 4;
    // prefetch slab 0
    cp16(&As[0][kks * LDT + mms],       &Ab[(size_t)kks * lda + m0 + mms]);
    cp16(&As[0][(kks + 8) * LDT + mms], &Ab[(size_t)(kks + 8) * lda + m0 + mms]);
    cp16(&Bs[0][kks * LDT + mms],       &Bw[(size_t)kks * ldb + nb + mms]);
    cp16(&Bs[0][(kks + 8) * LDT + mms], &Bw[(size_t)(kks + 8) * ldb + nb + mms]);
    CP_COMMIT;

#pragma unroll 1
    for (int it = 0; it < nIter; it++) {
        if (it + 1 < nIter) {
            int k0 = (it + 1) << 4, st = (it + 1) & 1;
            cp16(&As[st][kks * LDT + mms],       &Ab[(size_t)(k0 + kks) * lda + m0 + mms]);
            cp16(&As[st][(kks + 8) * LDT + mms], &Ab[(size_t)(k0 + kks + 8) * lda + m0 + mms]);
            cp16(&Bs[st][kks * LDT + mms],       &Bw[(size_t)(k0 + kks) * ldb + nb + mms]);
            cp16(&Bs[st][(kks + 8) * LDT + mms], &Bw[(size_t)(k0 + kks + 8) * ldb + nb + mms]);
        }
        CP_COMMIT;
        CP_WAIT1;
        __syncthreads();
        int st = it & 1;
#pragma unroll
        for (int ks = 0; ks < 16; ks += 8) {
            uint32_t a[4][4], b[4][2];
#pragma unroll
            for (int mf = 0; mf < 4; mf++) {
                int r = wm0 + mf * 16 + g;
                a[mf][0] = __float_as_uint(As[st][(ks + tig) * LDT + r]);
                a[mf][1] = __float_as_uint(As[st][(ks + tig) * LDT + r + 8]);
                a[mf][2] = __float_as_uint(As[st][(ks + tig + 4) * LDT + r]);
                a[mf][3] = __float_as_uint(As[st][(ks + tig + 4) * LDT + r + 8]);
            }
#pragma unroll
            for (int nf = 0; nf < 4; nf++) {
                int c = wn0 + nf * 8 + g;
                b[nf][0] = __float_as_uint(Bs[st][(ks + tig) * LDT + c]);
                b[nf][1] = __float_as_uint(Bs[st][(ks + tig + 4) * LDT + c]);
            }
#pragma unroll
            for (int mf = 0; mf < 4; mf++)
#pragma unroll
                for (int nf = 0; nf < 4; nf++)
                    mma_tf32(acc[mf][nf], a[mf], b[nf]);
        }
        __syncthreads();
    }

    bool doRound = (n0 >= roundCol);
#pragma unroll
    for (int mf = 0; mf < 4; mf++) {
        int row = m0 + wm0 + mf * 16 + g;
#pragma unroll
        for (int nf = 0; nf < 4; nf++) {
            int col = n0 + wn0 + nf * 8 + 2 * tig;
            float4 v = acc[mf][nf];
            if (doRound) v = to_tf32_4(v);
            *(float2*)&Cb[(size_t)row * ldc + col]       = make_float2(v.x, v.y);
            *(float2*)&Cb[(size_t)(row + 8) * ldc + col] = make_float2(v.z, v.w);
        }
    }
}

// ---------------- projection GEMM, double-buffered: A row-major [M,256] pre-rounded ----------------
__global__ __launch_bounds__(256) void proj_tf32(
    const float* __restrict__ A, const float* __restrict__ Bw,
    const float* __restrict__ bias, float* __restrict__ out, int cOff)
{
    __shared__ float As[2][128 * LDA2];
    __shared__ float Bs[2][16 * LDT];
    int n0 = blockIdx.x * 128, m0 = blockIdx.y * 128;
    int tid  = threadIdx.x;
    int lane = tid & 31, wid = tid >> 5;
    int g = lane >> 2, tig = lane & 3;
    int wm0 = (wid & 1) * 64;
    int wn0 = (wid >> 1) * 32;

    float4 acc[4][4];
#pragma unroll
    for (int i = 0; i < 4; i++)
#pragma unroll
        for (int j = 0; j < 4; j++) acc[i][j] = make_float4(0.f, 0.f, 0.f, 0.f);

    // staging indices: A rows (per thread 2 float4), B rows
    int mmA = tid >> 1;                  // i=0 rows 0..127 (two threads per row)
    int kqA = (tid & 1) * 4;             // +8 for second chunk
    int kkB = tid >> 5;
    int nnB = (tid & 31) * 4;

#define PROJ_PREFETCH(k0, st)                                                          \
    cp16(&As[st][mmA * LDA2 + kqA],     &A[(size_t)(m0 + mmA) * 256 + (k0) + kqA]);    \
    cp16(&As[st][mmA * LDA2 + kqA + 8], &A[(size_t)(m0 + mmA) * 256 + (k0) + kqA + 8]);\
    cp16(&Bs[st][kkB * LDT + nnB],       &Bw[(size_t)((k0) + kkB) * 256 + n0 + nnB]);  \
    cp16(&Bs[st][(kkB + 8) * LDT + nnB], &Bw[(size_t)((k0) + kkB + 8) * 256 + n0 + nnB]);

    PROJ_PREFETCH(0, 0);
    CP_COMMIT;

#pragma unroll 1
    for (int it = 0; it < 16; it++) {
        if (it + 1 < 16) {
            int k0 = (it + 1) << 4, st = (it + 1) & 1;
            PROJ_PREFETCH(k0, st);
        }
        CP_COMMIT;
        CP_WAIT1;
        __syncthreads();
        int st = it & 1;
#pragma unroll
        for (int ks = 0; ks < 16; ks += 8) {
            uint32_t a[4][4], b[4][2];
#pragma unroll
            for (int mf = 0; mf < 4; mf++) {
                int r = wm0 + mf * 16 + g;
                a[mf][0] = __float_as_uint(As[st][r * LDA2 + ks + tig]);
                a[mf][1] = __float_as_uint(As[st][(r + 8) * LDA2 + ks + tig]);
                a[mf][2] = __float_as_uint(As[st][r * LDA2 + ks + tig + 4]);
                a[mf][3] = __float_as_uint(As[st][(r + 8) * LDA2 + ks + tig + 4]);
            }
#pragma unroll
            for (int nf = 0; nf < 4; nf++) {
                int c = wn0 + nf * 8 + g;
                b[nf][0] = __float_as_uint(Bs[st][(ks + tig) * LDT + c]);
                b[nf][1] = __float_as_uint(Bs[st][(ks + tig + 4) * LDT + c]);
            }
#pragma unroll
            for (int mf = 0; mf < 4; mf++)
#pragma unroll
                for (int nf = 0; nf < 4; nf++)
                    mma_tf32(acc[mf][nf], a[mf], b[nf]);
        }
        __syncthreads();
    }

    // store transposed into (B, 512, 64, 64) with bias
#pragma unroll
    for (int nf = 0; nf < 4; nf++) {
        int n  = wn0 + nf * 8 + 2 * tig;
        float bv0 = bias[n0 + n], bv1 = bias[n0 + n + 1];
        size_t ch0 = (size_t)(cOff + n0 + n) * HWTOK;
#pragma unroll
        for (int mf = 0; mf < 4; mf++) {
            int m = m0 + wm0 + mf * 16 + g;
            int b0i = m >> 12, tok0 = m & 4095;
            int b1i = (m + 8) >> 12, tok1 = (m + 8) & 4095;
            size_t base0 = (size_t)b0i * (512 * HWTOK);
            size_t base1 = (size_t)b1i * (512 * HWTOK);
            out[base0 + ch0 + tok0]         = acc[mf][nf].x + bv0;
            out[base0 + ch0 + HWTOK + tok0] = acc[mf][nf].y + bv1;
            out[base1 + ch0 + tok1]         = acc[mf][nf].z + bv0;
            out[base1 + ch0 + HWTOK + tok1] = acc[mf][nf].w + bv1;
        }
    }
#undef PROJ_PREFETCH
}

// ---------------- hi-fi window attention: one warp per (b, window, head) ----------------
__global__ __launch_bounds__(128) void hi_attn_kernel()
{
    int wgl  = blockIdx.x * 4 + (threadIdx.x >> 5);
    int lane = threadIdx.x & 31;
    int b    = wgl >> 12;
    int rem  = wgl & 4095;
    int g    = rem >> 2;
    int head = rem & 3;
    int gh = g >> 5, gw = g & 31;

    float2 q[4], k[4], v[4];
    int tok[4];
#pragma unroll
    for (int n = 0; n < 4; n++) {
        int hh = gh * 2 + (n >> 1);
        int ww = gw * 2 + (n & 1);
        tok[n] = hh * 64 + ww;
        const float* base = g_qkvq + (size_t)(b * HWTOK + tok[n]) * 1024 + head * 64 + lane * 2;
        q[n] = *(const float2*)(base);
        k[n] = *(const float2*)(base + 256);
        v[n] = *(const float2*)(base + 512);
    }
    float s[4][4];
#pragma unroll
    for (int i = 0; i < 4; i++)
#pragma unroll
        for (int j = 0; j < 4; j++)
            s[i][j] = q[i].x * k[j].x + q[i].y * k[j].y;
#pragma unroll
    for (int off = 16; off; off >>= 1)
#pragma unroll
        for (int i = 0; i < 4; i++)
#pragma unroll
            for (int j = 0; j < 4; j++)
                s[i][j] += __shfl_xor_sync(0xffffffffu, s[i][j], off);

#pragma unroll
    for (int i = 0; i < 4; i++) {
        float s0 = s[i][0] * ATT_SCALE, s1 = s[i][1] * ATT_SCALE;
        float s2 = s[i][2] * ATT_SCALE, s3 = s[i][3] * ATT_SCALE;
        float mx = fmaxf(fmaxf(s0, s1), fmaxf(s2, s3));
        float p0 = __expf(s0 - mx), p1 = __expf(s1 - mx);
        float p2 = __expf(s2 - mx), p3 = __expf(s3 - mx);
        float inv = 1.f / (p0 + p1 + p2 + p3);
        float ox = (p0 * v[0].x + p1 * v[1].x + p2 * v[2].x + p3 * v[3].x) * inv;
        float oy = (p0 * v[0].y + p1 * v[1].y + p2 * v[2].y + p3 * v[3].y) * inv;
        *(float2*)&g_hiat[(size_t)(b * HWTOK + tok[i]) * HDIM + head * 64 + lane * 2] =
            make_float2(to_tf32(ox), to_tf32(oy));
    }
}

// ---------------- lo-fi attention: flash-style tf32 mma, cp.async double-buffered K/V ----------------
#define LDK 68
#define KVST (64 * LDK)
#define LO_SMEM ((4 * KVST + 128 * LDK) * 4)

__global__ __launch_bounds__(256, 2) void lo_attn_mma()
{
    extern __shared__ float sm[];
    float* Ks = sm;                 // [2][64*LDK]
    float* Vs = sm + 2 * KVST;      // [2][64*LDK]
    float* Ps = sm + 4 * KVST;      // [128*LDK], Q staging then P

    int bh = blockIdx.y;
    int b = bh >> 2, head = bh & 3;
    int q0 = blockIdx.x * 128;
    int tid  = threadIdx.x;
    int lane = tid & 31, wid = tid >> 5;
    int g = lane >> 2, tig = lane & 3;
    int rr = wid * 16 + g;

#define LO_LOAD_KV(ch, st)                                                             \
    _Pragma("unroll")                                                                  \
    for (int i = 0; i < 4; i++) {                                                      \
        int f = tid + i * 256; int r = f >> 4, dq = (f & 15) * 4;                      \
        size_t base = (size_t)(b * GWIN + (ch) * 64 + r) * 512 + head * 64 + dq;       \
        cp16(&Ks[(st) * KVST + r * LDK + dq], &g_lkv[base]);                           \
        cp16(&Vs[(st) * KVST + r * LDK + dq], &g_lkv[base + 256]);                     \
    }

    // stage Q (pre-rounded) via cp.async
#pragma unroll
    for (int i = 0; i < 8; i++) {
        int f = tid + i * 256;
        int r = f >> 4, dq = (f & 15) * 4;
        cp16(&Ps[r * LDK + dq],
             &g_qkvq[(size_t)(b * HWTOK + q0 + r) * 1024 + 768 + head * 64 + dq]);
    }
    CP_COMMIT;
    LO_LOAD_KV(0, 0);
    CP_COMMIT;
    CP_WAIT1;          // Q group done
    __syncthreads();

    uint32_t qa[8][4];
#pragma unroll
    for (int kf = 0; kf < 8; kf++) {
        qa[kf][0] = __float_as_uint(Ps[rr * LDK + kf * 8 + tig]);
        qa[kf][1] = __float_as_uint(Ps[(rr + 8) * LDK + kf * 8 + tig]);
        qa[kf][2] = __float_as_uint(Ps[rr * LDK + kf * 8 + tig + 4]);
        qa[kf][3] = __float_as_uint(Ps[(rr + 8) * LDK + kf * 8 + tig + 4]);
    }

    float4 o[8];
#pragma unroll
    for (int nf = 0; nf < 8; nf++) o[nf] = make_float4(0.f, 0.f, 0.f, 0.f);
    float m_lo = -1e30f, m_hi = -1e30f, l_lo = 0.f, l_hi = 0.f;

#pragma unroll 1
    for (int ch = 0; ch < 16; ch++) {
        if (ch + 1 < 16) { LO_LOAD_KV(ch + 1, (ch + 1) & 1); }
        CP_COMMIT;
        CP_WAIT1;
        __syncthreads();   // also guards: all qa loads done before Ps overwritten
        int st = ch & 1;
        const float* Kc = Ks + st * KVST;
        const float* Vc = Vs + st * KVST;

        // ---- S = Q @ K^T ----
        float4 s[8];
#pragma unroll
        for (int nf = 0; nf < 8; nf++) s[nf] = make_float4(0.f, 0.f, 0.f, 0.f);
#pragma unroll
        for (int kf = 0; kf < 8; kf++) {
#pragma unroll
            for (int nf = 0; nf < 8; nf++) {
                uint32_t bb[2];
                bb[0] = __float_as_uint(Kc[(nf * 8 + g) * LDK + kf * 8 + tig]);
                bb[1] = __float_as_uint(Kc[(nf * 8 + g) * LDK + kf * 8 + tig + 4]);
                mma_tf32(s[nf], qa[kf], bb);
            }
        }

        // ---- online softmax ----
        float mx_lo = -1e30f, mx_hi = -1e30f;
#pragma unroll
        for (int nf = 0; nf < 8; nf++) {
            s[nf].x *= ATT_SCALE; s[nf].y *= ATT_SCALE;
            s[nf].z *= ATT_SCALE; s[nf].w *= ATT_SCALE;
            mx_lo = fmaxf(mx_lo, fmaxf(s[nf].x, s[nf].y));
            mx_hi = fmaxf(mx_hi, fmaxf(s[nf].z, s[nf].w));
        }
        mx_lo = fmaxf(mx_lo, __shfl_xor_sync(0xffffffffu, mx_lo, 1));
        mx_lo = fmaxf(mx_lo, __shfl_xor_sync(0xffffffffu, mx_lo, 2));
        mx_hi = fmaxf(mx_hi, __shfl_xor_sync(0xffffffffu, mx_hi, 1));
        mx_hi = fmaxf(mx_hi, __shfl_xor_sync(0xffffffffu, mx_hi, 2));

        float mn_lo = fmaxf(m_lo, mx_lo);
        float mn_hi = fmaxf(m_hi, mx_hi);
        float fac_lo = __expf(m_lo - mn_lo);
        float fac_hi = __expf(m_hi - mn_hi);
        m_lo = mn_lo; m_hi = mn_hi;

        float sum_lo = 0.f, sum_hi = 0.f;
#pragma unroll
        for (int nf = 0; nf < 8; nf++) {
            float p0 = __expf(s[nf].x - mn_lo);
            float p1 = __expf(s[nf].y - mn_lo);
            float p2 = __expf(s[nf].z - mn_hi);
            float p3 = __expf(s[nf].w - mn_hi);
            sum_lo += p0 + p1; sum_hi += p2 + p3;
            int col = nf * 8 + 2 * tig;
            *(float2*)&Ps[rr * LDK + col]       = make_float2(to_tf32(p0), to_tf32(p1));
            *(float2*)&Ps[(rr + 8) * LDK + col] = make_float2(to_tf32(p2), to_tf32(p3));
        }
        sum_lo += __shfl_xor_sync(0xffffffffu, sum_lo, 1);
        sum_lo += __shfl_xor_sync(0xffffffffu, sum_lo, 2);
        sum_hi += __shfl_xor_sync(0xffffffffu, sum_hi, 1);
        sum_hi += __shfl_xor_sync(0xffffffffu, sum_hi, 2);
        l_lo = l_lo * fac_lo + sum_lo;
        l_hi = l_hi * fac_hi + sum_hi;

#pragma unroll
        for (int nf = 0; nf < 8; nf++) {
            o[nf].x *= fac_lo; o[nf].y *= fac_lo;
            o[nf].z *= fac_hi; o[nf].w *= fac_hi;
        }
        __syncwarp();   // warp-private Ps rows visible

        // ---- O += P @ V ----
#pragma unroll
        for (int kf = 0; kf < 8; kf++) {
            uint32_t pa[4];
            pa[0] = __float_as_uint(Ps[rr * LDK + kf * 8 + tig]);
            pa[1] = __float_as_uint(Ps[(rr + 8) * LDK + kf * 8 + tig]);
            pa[2] = __float_as_uint(Ps[rr * LDK + kf * 8 + tig + 4]);
            pa[3] = __float_as_uint(Ps[(rr + 8) * LDK + kf * 8 + tig + 4]);
#pragma unroll
            for (int nf = 0; nf < 8; nf++) {
                uint32_t bb[2];
                bb[0] = __float_as_uint(Vc[(kf * 8 + tig) * LDK + nf * 8 + g]);
                bb[1] = __float_as_uint(Vc[(kf * 8 + tig + 4) * LDK + nf * 8 + g]);
                mma_tf32(o[nf], pa, bb);
            }
        }
        __syncthreads();  // all warps done with Kc/Vc before next overwrite
    }

    float inv_lo = 1.f / l_lo;
    float inv_hi = 1.f / l_hi;
    size_t row0 = (size_t)(b * HWTOK + q0 + rr);
#pragma unroll
    for (int nf = 0; nf < 8; nf++) {
        int col = head * 64 + nf * 8 + 2 * tig;
        *(float2*)&g_loat[row0 * LDIM + col] =
            make_float2(to_tf32(o[nf].x * inv_lo), to_tf32(o[nf].y * inv_lo));
        *(float2*)&g_loat[(row0 + 8) * LDIM + col] =
            make_float2(to_tf32(o[nf].z * inv_hi), to_tf32(o[nf].w * inv_hi));
    }
#undef LO_LOAD_KV
}

// ---------------- launch ----------------
extern "C" void kernel_launch(void* const* d_in, const int* in_sizes, int n_in,
                              void* d_out, int out_size)
{
    (void)in_sizes; (void)n_in; (void)out_size;
    const float* x        = (const float*)d_in[0];
    const float* h_qkv_w  = (const float*)d_in[1];
    const float* h_proj_w = (const float*)d_in[2];
    const float* h_proj_b = (const float*)d_in[3];
    const float* l_q_w    = (const float*)d_in[4];
    const float* l_kv_w   = (const float*)d_in[5];
    const float* l_proj_w = (const float*)d_in[6];
    const float* l_proj_b = (const float*)d_in[7];
    float* out = (float*)d_out;

    float *xr, *wr, *pooledT, *qkvq, *lkv, *hiat, *loat;
    cudaGetSymbolAddress((void**)&xr,      g_xr);
    cudaGetSymbolAddress((void**)&wr,      g_wr);
    cudaGetSymbolAddress((void**)&pooledT, g_pooledT);
    cudaGetSymbolAddress((void**)&qkvq,    g_qkvq);
    cudaGetSymbolAddress((void**)&lkv,     g_lkv);
    cudaGetSymbolAddress((void**)&hiat,    g_hiat);
    cudaGetSymbolAddress((void**)&loat,    g_loat);

    cudaFuncSetAttribute(lo_attn_mma, cudaFuncAttributeMaxDynamicSharedMemorySize, LO_SMEM);

    // 0. pre-round x + weights to tf32
    round_x_kernel<<<(BATCH * CDIM * HWTOK / 4) / 256, 256>>>(x);
    round_w_kernel<<<(W_TOT / 4) / 256, 256>>>(h_qkv_w, l_q_w, l_kv_w, h_proj_w, l_proj_w);

    // 1. window pooling (rounded output)
    pool_kernel<<<(CDIM * BATCH * GWIN) / 256, 256>>>(x);

    // 2. fused qkv_hi | q_lo GEMM: per batch (4096 x 512) @ (512 x 1024); round cols >= 768
    gemm_tf32<<<dim3(8, 32, 4), 256>>>(
        xr, HWTOK, (size_t)CDIM * HWTOK,
        wr + W_QKV, 768, wr + W_LQ, 256, 768,
        CDIM, qkvq, 1024, (size_t)HWTOK * 1024, 768);

    // 3. lo-fi kv GEMM: (4096 x 512) @ (512 x 512); round all
    gemm_tf32<<<dim3(4, 32, 1), 256>>>(
        pooledT, BATCH * GWIN, 0,
        wr + W_LKV, 512, wr + W_LKV, 512, 1 << 30,
        CDIM, lkv, 512, 0, 0);

    // 4. hi-fi window attention (rounded output)
    hi_attn_kernel<<<4096, 128>>>();

    // 5. hi-fi projection -> out channels [0,256)
    proj_tf32<<<dim3(2, 128), 256>>>(hiat, wr + W_HP, h_proj_b, out, 0);

    // 6. lo-fi attention (tensor-core flash, rounded output)
    lo_attn_mma<<<dim3(32, 16), 256, LO_SMEM>>>();

    // 7. lo-fi projection -> out channels [256,512)
    proj_tf32<<<dim3(2, 128), 256>>>(loat, wr + W_LP, l_proj_b, out, 256);
}